// round 4
// baseline (speedup 1.0000x reference)
#include <cuda_runtime.h>
#include <cstdint>

typedef unsigned long long ull;

// Problem dims (fixed by the dataset's setup_inputs)
constexpr int B   = 8;
constexpr int NC  = 19;
constexpr int HC  = 32;
constexpr int WC  = 64;
constexpr int CF  = 256;
constexpr int HF  = 128;
constexpr int WF  = 256;
constexpr int HID = 256;
constexpr int HW  = HF * WF;         // 32768
constexpr int NPTS = 2048;           // min(2048, HW/4)
constexpr int CIN1 = CF + NC;        // 275
constexpr int PPB  = 32;             // points per block in MLP kernel
constexpr int BLKS_PER_BATCH = NPTS / PPB;  // 64
constexpr int KC   = 32;             // K-chunk for weight tiles
constexpr int OSTR = 260;            // padded out-stride of weight tile (words)

// Scratch (static device memory — no allocation)
__device__ float g_unc[B * HW];
__device__ int   g_idx[B * NPTS];
__device__ int   g_tie[B * HW];

// ---------------------------------------------------------------------------
// f32x2 packed helpers
// ---------------------------------------------------------------------------
__device__ __forceinline__ ull fma2(ull a, ull b, ull c) {
    ull d;
    asm("fma.rn.f32x2 %0, %1, %2, %3;" : "=l"(d) : "l"(a), "l"(b), "l"(c));
    return d;
}
__device__ __forceinline__ ull pack2(float x) {
    ull r;
    asm("mov.b64 %0, {%1, %1};" : "=l"(r) : "f"(x));
    return r;
}
__device__ __forceinline__ void unpack2(ull v, float& x, float& y) {
    asm("mov.b64 {%0, %1}, %2;" : "=f"(x), "=f"(y) : "l"(v));
}

// ---------------------------------------------------------------------------
// Kernel A: bilinear upsample (align_corners) + uncertainty, smem-staged rows
// grid: B*HF blocks, 256 threads (one output row each)
// ---------------------------------------------------------------------------
__global__ void __launch_bounds__(WF) upsample_unc_kernel(
    const float* __restrict__ coarse, float* __restrict__ out,
    float* __restrict__ unc)
{
    __shared__ float sm[NC * 128];   // [c][r(2)][64]
    int w = threadIdx.x;
    int h = blockIdx.x & (HF - 1);
    int b = blockIdx.x >> 7;

    float yf = (float)h * ((float)(HC - 1) / (float)(HF - 1));
    int y0 = (int)floorf(yf); y0 = max(0, min(y0, HC - 1));
    int y1 = min(y0 + 1, HC - 1);
    float wy = yf - (float)y0;

    const float* cb = coarse + (size_t)b * NC * HC * WC;
    for (int j = w; j < NC * 128; j += WF) {
        int c = j >> 7, r = (j >> 6) & 1, x = j & 63;
        sm[j] = cb[c * (HC * WC) + (r ? y1 : y0) * WC + x];
    }
    __syncthreads();

    float xf = (float)w * ((float)(WC - 1) / (float)(WF - 1));
    int x0 = (int)floorf(xf); x0 = max(0, min(x0, WC - 1));
    int x1 = min(x0 + 1, WC - 1);
    float wx = xf - (float)x0;

    float v[NC];
    float vmax = -3.4e38f;
#pragma unroll
    for (int c = 0; c < NC; c++) {
        float c00 = sm[c * 128 + x0],      c10 = sm[c * 128 + 64 + x0];
        float c01 = sm[c * 128 + x1],      c11 = sm[c * 128 + 64 + x1];
        float r0 = c00 * (1.f - wy) + c10 * wy;
        float r1 = c01 * (1.f - wy) + c11 * wy;
        float val = r0 * (1.f - wx) + r1 * wx;
        v[c] = val;
        vmax = fmaxf(vmax, val);
        out[((size_t)(b * NC + c) * HF + h) * WF + w] = val;
    }
    float s = 0.f;
#pragma unroll
    for (int c = 0; c < NC; c++) s += expf(v[c] - vmax);
    unc[b * HW + h * WF + w] = -1.0f / s;
}

// ---------------------------------------------------------------------------
// Kernel B: exact top-NPTS per batch via 4x8-bit radix select.
// Keys register-cached (1 global read), histogram via warp-aggregated atomics.
// ---------------------------------------------------------------------------
__device__ __forceinline__ unsigned fkey(float f) {
    unsigned u = __float_as_uint(f);
    return (u & 0x80000000u) ? ~u : (u | 0x80000000u);
}

constexpr int KPT = HW / 1024;   // 32 keys per thread

__global__ void __launch_bounds__(1024) topk_kernel() {
    int b = blockIdx.x;
    int tid = threadIdx.x;
    int lane = tid & 31;
    const float* u = g_unc + b * HW;

    unsigned key[KPT];
#pragma unroll
    for (int i = 0; i < KPT; i++) key[i] = fkey(u[i * 1024 + tid]);

    __shared__ unsigned hist[256];
    __shared__ unsigned s_prefix;
    __shared__ unsigned s_mask;
    __shared__ int s_rem;
    __shared__ int cSel, cTie;

    if (tid == 0) { s_prefix = 0; s_mask = 0; s_rem = NPTS; cSel = 0; cTie = 0; }
    __syncthreads();

    for (int pass = 0; pass < 4; pass++) {
        int shift = (3 - pass) * 8;
        if (tid < 256) hist[tid] = 0;
        __syncthreads();
        unsigned mask = s_mask, pref = s_prefix;
#pragma unroll
        for (int i = 0; i < KPT; i++) {
            unsigned k = key[i];
            bool act = (k & mask) == pref;
            unsigned bin = act ? ((k >> shift) & 255u) : 0xFFFFFFFFu;
            unsigned same = __match_any_sync(0xFFFFFFFFu, bin);
            if (act && (unsigned)(__ffs(same) - 1) == (unsigned)lane)
                atomicAdd(&hist[bin], (unsigned)__popc(same));
        }
        __syncthreads();
        if (tid == 0) {
            int need = s_rem;
            unsigned cum = 0;
            int sel = 0;
            for (int bin = 255; bin >= 0; bin--) {
                unsigned h = hist[bin];
                if (cum + h >= (unsigned)need) { sel = bin; s_rem = need - (int)cum; break; }
                cum += h;
            }
            s_prefix = pref | ((unsigned)sel << shift);
            s_mask = mask | (0xFFu << shift);
        }
        __syncthreads();
    }

    unsigned T = s_prefix;
    int R = s_rem;
    int* tie = g_tie + b * HW;

#pragma unroll
    for (int i = 0; i < KPT; i++) {
        unsigned k = key[i];
        int idx = i * 1024 + tid;
        if (k > T) {
            int p = atomicAdd(&cSel, 1);
            g_idx[b * NPTS + p] = idx;
        } else if (k == T) {
            int p = atomicAdd(&cTie, 1);
            tie[p] = idx;
        }
    }
    __syncthreads();
    int E = cTie, base = cSel;   // base + R == NPTS by radix-select invariant
    for (int t = tid; t < E; t += 1024) {
        int my = tie[t];
        int r = 0;
        for (int j = 0; j < E; j++) r += (tie[j] < my) ? 1 : 0;
        if (r < R) g_idx[b * NPTS + base + r] = my;
    }
}

// ---------------------------------------------------------------------------
// Kernel C: gather + 3-layer MLP (smem-staged weight tiles w/ register
// prefetch double-buffering, f32x2 FMA) + scatter
// ---------------------------------------------------------------------------
constexpr int WT_FLOATS = KC * OSTR;                              // 8320
constexpr int SMEM_FLOATS = CIN1 * PPB + HID * PPB + WT_FLOATS;   // 25312
constexpr size_t MLP_SMEM = SMEM_FLOATS * sizeof(float) + PPB * sizeof(int);

// Coalesced global->register load of a KCxHID weight tile slice.
__device__ __forceinline__ void ld_wtile(
    const float* __restrict__ W, int CIN, int c0, int kc, float* r, int tid)
{
    int k = tid & 31;
    int ob = tid >> 5;
    if (k < kc) {
#pragma unroll
        for (int i = 0; i < 32; i++)
            r[i] = __ldg(&W[(i * 8 + ob) * CIN + c0 + k]);
    } else {
#pragma unroll
        for (int i = 0; i < 32; i++) r[i] = 0.f;
    }
}

__device__ __forceinline__ void st_wtile(float* wt, const float* r, int tid)
{
    int k = tid & 31;
    int ob = tid >> 5;
#pragma unroll
    for (int i = 0; i < 32; i++)
        wt[k * OSTR + i * 8 + ob] = r[i];
}

template <int KCC>
__device__ __forceinline__ void mma_chunk(
    const float* wt, const float* pf, int c0, int o0, int poff, ull* acc)
{
#pragma unroll 8
    for (int c = 0; c < KCC; c++) {
        float4 wv = *reinterpret_cast<const float4*>(&wt[c * OSTR + o0]);
        ull p0 = pack2(wv.x), p1 = pack2(wv.y), p2 = pack2(wv.z), p3 = pack2(wv.w);
        const ull* row = reinterpret_cast<const ull*>(&pf[(c0 + c) * PPB + poff]);
        ull d0 = row[0], d1 = row[1], d2 = row[2], d3 = row[3];
        acc[0]  = fma2(p0, d0, acc[0]);  acc[1]  = fma2(p0, d1, acc[1]);
        acc[2]  = fma2(p0, d2, acc[2]);  acc[3]  = fma2(p0, d3, acc[3]);
        acc[4]  = fma2(p1, d0, acc[4]);  acc[5]  = fma2(p1, d1, acc[5]);
        acc[6]  = fma2(p1, d2, acc[6]);  acc[7]  = fma2(p1, d3, acc[7]);
        acc[8]  = fma2(p2, d0, acc[8]);  acc[9]  = fma2(p2, d1, acc[9]);
        acc[10] = fma2(p2, d2, acc[10]); acc[11] = fma2(p2, d3, acc[11]);
        acc[12] = fma2(p3, d0, acc[12]); acc[13] = fma2(p3, d1, acc[13]);
        acc[14] = fma2(p3, d2, acc[14]); acc[15] = fma2(p3, d3, acc[15]);
    }
}

__global__ void __launch_bounds__(256, 2) mlp_kernel(
    const float* __restrict__ fine,
    const float* __restrict__ w1, const float* __restrict__ b1,
    const float* __restrict__ w2, const float* __restrict__ b2,
    const float* __restrict__ w3, const float* __restrict__ b3,
    float* __restrict__ out)
{
    extern __shared__ float smem[];
    float* pf  = smem;                      // [CIN1][PPB]; reused as h2 [HID][PPB]
    float* h1s = pf + CIN1 * PPB;           // [HID][PPB]
    float* wt  = h1s + HID * PPB;           // [KC][OSTR]
    int*  sidx = (int*)(wt + WT_FLOATS);

    int tid = threadIdx.x;
    int b = blockIdx.x >> 6;                       // / BLKS_PER_BATCH
    int pbase = (blockIdx.x & (BLKS_PER_BATCH - 1)) * PPB;

    if (tid < PPB) sidx[tid] = g_idx[b * NPTS + pbase + tid];
    __syncthreads();

    // gather fine features: thread = channel (inherently scattered gather)
    {
        const float* fb = fine + (size_t)b * CF * HW + (size_t)tid * HW;
#pragma unroll 8
        for (int p = 0; p < PPB; p++) pf[tid * PPB + p] = fb[sidx[p]];
    }
    // gather coarse_up (already in out)
    if (tid < NC * 8) {
        int c = tid >> 3;
        int p0 = (tid & 7) * 4;
        const float* ob = out + (size_t)(b * NC + c) * HW;
#pragma unroll
        for (int q = 0; q < 4; q++) pf[(CF + c) * PPB + p0 + q] = ob[sidx[p0 + q]];
    }

    int og = tid & 63;      // output group: outputs 4*og .. 4*og+3
    int pg = tid >> 6;      // point group: points 8*pg .. 8*pg+7
    int o0 = og * 4;
    int poff = pg * 8;

    float rw[32];
    ull acc[16];

    // ---- layer 1: [HID, CIN1] = 8 full chunks + 19 remainder ----
#pragma unroll
    for (int i = 0; i < 16; i++) acc[i] = 0ull;
    ld_wtile(w1, CIN1, 0, KC, rw, tid);
    st_wtile(wt, rw, tid);
    for (int ch = 0; ch < 8; ch++) {
        if (ch < 7) ld_wtile(w1, CIN1, (ch + 1) * KC, KC, rw, tid);
        else        ld_wtile(w1, CIN1, 8 * KC, CIN1 - 8 * KC, rw, tid);
        __syncthreads();                 // wt ready (also orders gather -> mma)
        mma_chunk<KC>(wt, pf, ch * KC, o0, poff, acc);
        __syncthreads();                 // wt consumed
        st_wtile(wt, rw, tid);
    }
    // remainder chunk (kc = 19) ; prefetch first w2 tile
    ld_wtile(w2, HID, 0, KC, rw, tid);
    __syncthreads();
    mma_chunk<CIN1 - 8 * KC>(wt, pf, 8 * KC, o0, poff, acc);
    __syncthreads();
    st_wtile(wt, rw, tid);

#pragma unroll
    for (int k = 0; k < 4; k++) {
        float bk = b1[o0 + k];
#pragma unroll
        for (int j = 0; j < 4; j++) {
            float x, y;
            unpack2(acc[k * 4 + j], x, y);
            x = fmaxf(x + bk, 0.f);
            y = fmaxf(y + bk, 0.f);
            h1s[(o0 + k) * PPB + poff + 2 * j]     = x;
            h1s[(o0 + k) * PPB + poff + 2 * j + 1] = y;
        }
    }

    // ---- layer 2: [HID, HID] = 8 full chunks, h1s -> (pf reused as h2) ----
#pragma unroll
    for (int i = 0; i < 16; i++) acc[i] = 0ull;
    for (int ch = 0; ch < 8; ch++) {
        if (ch < 7) ld_wtile(w2, HID, (ch + 1) * KC, KC, rw, tid);
        __syncthreads();                 // wt + h1s visible
        mma_chunk<KC>(wt, h1s, ch * KC, o0, poff, acc);
        __syncthreads();
        if (ch < 7) st_wtile(wt, rw, tid);
    }
    // pf (layer-1 data) reads long done; safe to overwrite as h2
#pragma unroll
    for (int k = 0; k < 4; k++) {
        float bk = b2[o0 + k];
#pragma unroll
        for (int j = 0; j < 4; j++) {
            float x, y;
            unpack2(acc[k * 4 + j], x, y);
            x = fmaxf(x + bk, 0.f);
            y = fmaxf(y + bk, 0.f);
            pf[(o0 + k) * PPB + poff + 2 * j]     = x;
            pf[(o0 + k) * PPB + poff + 2 * j + 1] = y;
        }
    }
    __syncthreads();

    // ---- layer 3: [NC, HID] + scatter (w3 reads are warp-uniform -> bcast) ----
    for (int t = tid; t < NC * PPB; t += 256) {
        int o = t >> 5;       // PPB = 32
        int p = t & 31;
        float a = b3[o];
        const float* wr = w3 + o * HID;
#pragma unroll 8
        for (int c = 0; c < HID; c++) a = fmaf(wr[c], pf[c * PPB + p], a);
        out[(size_t)(b * NC + o) * HW + sidx[p]] = a;
    }
}

// ---------------------------------------------------------------------------
extern "C" void kernel_launch(void* const* d_in, const int* in_sizes, int n_in,
                              void* d_out, int out_size)
{
    (void)in_sizes; (void)n_in; (void)out_size;
    const float* coarse = (const float*)d_in[0];
    const float* fine   = (const float*)d_in[1];
    const float* w1     = (const float*)d_in[2];
    const float* b1     = (const float*)d_in[3];
    const float* w2     = (const float*)d_in[4];
    const float* b2     = (const float*)d_in[5];
    const float* w3     = (const float*)d_in[6];
    const float* b3     = (const float*)d_in[7];
    float* out = (float*)d_out;

    static float* unc = nullptr;
    if (!unc) cudaGetSymbolAddress((void**)&unc, g_unc);

    static bool attr_done = false;
    if (!attr_done) {
        cudaFuncSetAttribute(mlp_kernel,
                             cudaFuncAttributeMaxDynamicSharedMemorySize,
                             (int)MLP_SMEM);
        attr_done = true;
    }

    upsample_unc_kernel<<<B * HF, WF>>>(coarse, out, unc);
    topk_kernel<<<B, 1024>>>();
    mlp_kernel<<<B * BLKS_PER_BATCH, 256, MLP_SMEM>>>(fine, w1, b1, w2, b2, w3, b3, out);
}

// round 6
// speedup vs baseline: 1.5496x; 1.5496x over previous
#include <cuda_runtime.h>
#include <cuda_bf16.h>
#include <cstdint>

constexpr int B = 8, NC = 19, HC = 32, WC = 64, CF = 256;
constexpr int HF = 128, WF = 256, HID = 256;
constexpr int HW = HF * WF, NPTS = 2048, CIN1 = CF + NC;   // 275
constexpr int K1P = 320;          // CIN1 padded to 32
constexpr int AKS = 328;          // A smem row stride (bf16 words)
constexpr int WKS = 40;           // W chunk row stride (bf16 words)

__device__ float g_unc[B * HW];
__device__ int   g_idx[B * NPTS];
__device__ int   g_tie[B * HW];

// ---------------- Kernel A: upsample + uncertainty ----------------
__global__ void __launch_bounds__(WF) upsample_unc_kernel(
    const float* __restrict__ coarse, float* __restrict__ out, float* __restrict__ unc)
{
    __shared__ float sm[NC * 128];
    int w = threadIdx.x, h = blockIdx.x & (HF - 1), b = blockIdx.x >> 7;
    float yf = (float)h * ((float)(HC - 1) / (float)(HF - 1));
    int y0 = min(max((int)floorf(yf), 0), HC - 1);
    int y1 = min(y0 + 1, HC - 1);
    float wy = yf - (float)y0;
    const float* cb = coarse + (size_t)b * NC * HC * WC;
    for (int j = w; j < NC * 128; j += WF) {
        int c = j >> 7, r = (j >> 6) & 1, x = j & 63;
        sm[j] = cb[c * (HC * WC) + (r ? y1 : y0) * WC + x];
    }
    __syncthreads();
    float xf = (float)w * ((float)(WC - 1) / (float)(WF - 1));
    int x0 = min(max((int)floorf(xf), 0), WC - 1);
    int x1 = min(x0 + 1, WC - 1);
    float wx = xf - (float)x0;
    float v[NC], vmax = -3.4e38f;
#pragma unroll
    for (int c = 0; c < NC; c++) {
        float r0 = sm[c*128 + x0] * (1.f - wy) + sm[c*128 + 64 + x0] * wy;
        float r1 = sm[c*128 + x1] * (1.f - wy) + sm[c*128 + 64 + x1] * wy;
        float val = r0 * (1.f - wx) + r1 * wx;
        v[c] = val; vmax = fmaxf(vmax, val);
        out[((size_t)(b * NC + c) * HF + h) * WF + w] = val;
    }
    float s = 0.f;
#pragma unroll
    for (int c = 0; c < NC; c++) s += expf(v[c] - vmax);
    unc[b * HW + h * WF + w] = -1.0f / s;
}

// ---------------- Kernel B: top-NPTS radix select ----------------
__device__ __forceinline__ unsigned fkey(float f) {
    unsigned u = __float_as_uint(f);
    return (u & 0x80000000u) ? ~u : (u | 0x80000000u);
}
constexpr int KPT = HW / 1024;

__global__ void __launch_bounds__(1024) topk_kernel() {
    int b = blockIdx.x, tid = threadIdx.x, lane = tid & 31;
    const float* u = g_unc + b * HW;
    unsigned key[KPT];
#pragma unroll
    for (int i = 0; i < KPT; i++) key[i] = fkey(u[i * 1024 + tid]);

    __shared__ unsigned hist[256];
    __shared__ unsigned s_prefix, s_mask;
    __shared__ int s_rem, cSel, cTie;
    if (tid == 0) { s_prefix = 0; s_mask = 0; s_rem = NPTS; cSel = 0; cTie = 0; }
    __syncthreads();

    for (int pass = 0; pass < 4; pass++) {
        int shift = (3 - pass) * 8;
        if (tid < 256) hist[tid] = 0;
        __syncthreads();
        unsigned mask = s_mask, pref = s_prefix;
#pragma unroll
        for (int i = 0; i < KPT; i++) {
            unsigned k = key[i];
            bool act = (k & mask) == pref;
            unsigned bin = act ? ((k >> shift) & 255u) : 0xFFFFFFFFu;
            unsigned same = __match_any_sync(0xFFFFFFFFu, bin);
            if (act && (unsigned)(__ffs(same) - 1) == (unsigned)lane)
                atomicAdd(&hist[bin], (unsigned)__popc(same));
        }
        __syncthreads();
        if (tid == 0) {
            int need = s_rem; unsigned cum = 0; int sel = 0;
            for (int bin = 255; bin >= 0; bin--) {
                unsigned h = hist[bin];
                if (cum + h >= (unsigned)need) { sel = bin; s_rem = need - (int)cum; break; }
                cum += h;
            }
            s_prefix = pref | ((unsigned)sel << shift);
            s_mask = mask | (0xFFu << shift);
        }
        __syncthreads();
    }
    unsigned T = s_prefix;
    int R = s_rem;
    int* tie = g_tie + b * HW;
#pragma unroll
    for (int i = 0; i < KPT; i++) {
        unsigned k = key[i];
        int idx = i * 1024 + tid;
        if (k > T)       g_idx[b * NPTS + atomicAdd(&cSel, 1)] = idx;
        else if (k == T) tie[atomicAdd(&cTie, 1)] = idx;
    }
    __syncthreads();
    int E = cTie, base = cSel;
    for (int t = tid; t < E; t += 1024) {
        int my = tie[t], r = 0;
        for (int j = 0; j < E; j++) r += (tie[j] < my) ? 1 : 0;
        if (r < R) g_idx[b * NPTS + base + r] = my;
    }
}

// ---------------- MLP on mma.sync (bf16, 3-term split) ----------------
__device__ __forceinline__ void bf_split(float v, __nv_bfloat16& h, __nv_bfloat16& l) {
    h = __float2bfloat16(v);
    l = __float2bfloat16(v - __bfloat162float(h));
}

__device__ __forceinline__ void mma16816(float* d, const uint32_t* a, const uint32_t* b) {
    asm volatile(
        "mma.sync.aligned.m16n8k16.row.col.f32.bf16.bf16.f32 "
        "{%0,%1,%2,%3}, {%4,%5,%6,%7}, {%8,%9}, {%0,%1,%2,%3};"
        : "+f"(d[0]), "+f"(d[1]), "+f"(d[2]), "+f"(d[3])
        : "r"(a[0]), "r"(a[1]), "r"(a[2]), "r"(a[3]), "r"(b[0]), "r"(b[1]));
}

// smem byte offsets
constexpr int A_HI = 0;                              // 128*328*2 = 83968
constexpr int A_LO = 83968;
constexpr int W_HI = 167936;                         // 256*40*2 = 20480
constexpr int W_LO = 188416;
constexpr int S_IDX = 208896;                        // 128 ints
constexpr int SM_TOTAL = 209408 + 128;

__device__ __forceinline__ uint32_t lda(const char* sm, int base, int row, int col) {
    return *(const uint32_t*)(sm + base + (row * AKS + col) * 2);
}
__device__ __forceinline__ uint32_t ldw(const char* sm, int base, int n, int k) {
    return *(const uint32_t*)(sm + base + (n * WKS + k) * 2);
}

// stage a [rows][32] chunk of W (f32 -> bf16 hi/lo) into W bufs
__device__ __forceinline__ void stage_w(char* sm, const float* __restrict__ W,
                                        int cin, int nv, int rows, int k0, int tid)
{
    for (int idx = tid; idx < rows * 32; idx += 512) {
        int n = idx >> 5, kk = idx & 31, k = k0 + kk;
        float v = (n < nv && k < cin) ? W[n * cin + k] : 0.f;
        __nv_bfloat16 h, l; bf_split(v, h, l);
        *(__nv_bfloat16*)(sm + W_HI + (n * WKS + kk) * 2) = h;
        *(__nv_bfloat16*)(sm + W_LO + (n * WKS + kk) * 2) = l;
    }
}

__global__ void __launch_bounds__(512, 1) mlp_mma_kernel(
    const float* __restrict__ fine,
    const float* __restrict__ w1, const float* __restrict__ b1,
    const float* __restrict__ w2, const float* __restrict__ b2,
    const float* __restrict__ w3, const float* __restrict__ b3,
    float* __restrict__ out)
{
    extern __shared__ char sm[];
    int tid = threadIdx.x, wid = tid >> 5, lane = tid & 31;
    int wm = wid & 3, wn = wid >> 2;           // warp tile: rows 32*wm, cols 64*wn
    int b = blockIdx.x >> 4, tb = blockIdx.x & 15;
    int* sidx = (int*)(sm + S_IDX);

    if (tid < 128) sidx[tid] = g_idx[b * NPTS + tb * 128 + tid];
    __syncthreads();

    // ---- gather A[p][c] (hi/lo split) ----
    for (int idx = tid; idx < K1P * 128; idx += 512) {
        int p = idx & 127, c = idx >> 7;
        float v = 0.f;
        if (c < CF)        v = fine[((size_t)b * CF + c) * HW + sidx[p]];
        else if (c < CIN1) v = out[((size_t)b * NC + (c - CF)) * HW + sidx[p]];
        __nv_bfloat16 h, l; bf_split(v, h, l);
        *(__nv_bfloat16*)(sm + A_HI + (p * AKS + c) * 2) = h;
        *(__nv_bfloat16*)(sm + A_LO + (p * AKS + c) * 2) = l;
    }

    float acc[2][8][4];
    int qrow = lane >> 2, qk = 2 * (lane & 3);

    // ================= layers 1 & 2 =================
#pragma unroll 1
    for (int layer = 0; layer < 2; layer++) {
        const float* W   = layer ? w2 : w1;
        const float* bia = layer ? b2 : b1;
        int cin   = layer ? HID : CIN1;
        int kpad  = layer ? HID : K1P;
        int nstg  = kpad / 32;
#pragma unroll
        for (int t = 0; t < 2; t++)
#pragma unroll
            for (int u = 0; u < 8; u++)
#pragma unroll
                for (int q = 0; q < 4; q++) acc[t][u][q] = 0.f;

        for (int s = 0; s < nstg; s++) {
            __syncthreads();                       // prior mma done -> W overwrite safe
            stage_w(sm, W, cin, 256, 256, s * 32, tid);
            __syncthreads();
#pragma unroll
            for (int half = 0; half < 2; half++) {
                int kg = s * 32 + half * 16;       // global k into A
                int kl = half * 16;                // local k into W chunk
                uint32_t ah[2][4], al[2][4];
#pragma unroll
                for (int t = 0; t < 2; t++) {
                    int r = wm * 32 + t * 16 + qrow;
                    ah[t][0] = lda(sm, A_HI, r,     kg + qk);
                    ah[t][1] = lda(sm, A_HI, r + 8, kg + qk);
                    ah[t][2] = lda(sm, A_HI, r,     kg + qk + 8);
                    ah[t][3] = lda(sm, A_HI, r + 8, kg + qk + 8);
                    al[t][0] = lda(sm, A_LO, r,     kg + qk);
                    al[t][1] = lda(sm, A_LO, r + 8, kg + qk);
                    al[t][2] = lda(sm, A_LO, r,     kg + qk + 8);
                    al[t][3] = lda(sm, A_LO, r + 8, kg + qk + 8);
                }
#pragma unroll
                for (int u = 0; u < 8; u++) {
                    int n = wn * 64 + u * 8 + qrow;
                    uint32_t bh[2], bl[2];
                    bh[0] = ldw(sm, W_HI, n, kl + qk);
                    bh[1] = ldw(sm, W_HI, n, kl + qk + 8);
                    bl[0] = ldw(sm, W_LO, n, kl + qk);
                    bl[1] = ldw(sm, W_LO, n, kl + qk + 8);
#pragma unroll
                    for (int t = 0; t < 2; t++) {
                        mma16816(acc[t][u], ah[t], bh);
                        mma16816(acc[t][u], al[t], bh);
                        mma16816(acc[t][u], ah[t], bl);
                    }
                }
            }
        }
        __syncthreads();    // all mma reads of A done before overwrite

        // epilogue: bias + relu + split back into A
#pragma unroll
        for (int t = 0; t < 2; t++) {
#pragma unroll
            for (int u = 0; u < 8; u++) {
                int r  = wm * 32 + t * 16 + qrow;
                int cc = wn * 64 + u * 8 + qk;
                float bb0 = __ldg(&bia[cc]), bb1 = __ldg(&bia[cc + 1]);
                float v0 = fmaxf(acc[t][u][0] + bb0, 0.f);
                float v1 = fmaxf(acc[t][u][1] + bb1, 0.f);
                float v2 = fmaxf(acc[t][u][2] + bb0, 0.f);
                float v3 = fmaxf(acc[t][u][3] + bb1, 0.f);
                __nv_bfloat16 h0, l0, h1, l1;
                bf_split(v0, h0, l0); bf_split(v1, h1, l1);
                *(__nv_bfloat162*)(sm + A_HI + (r * AKS + cc) * 2) = __nv_bfloat162(h0, h1);
                *(__nv_bfloat162*)(sm + A_LO + (r * AKS + cc) * 2) = __nv_bfloat162(l0, l1);
                bf_split(v2, h0, l0); bf_split(v3, h1, l1);
                *(__nv_bfloat162*)(sm + A_HI + ((r + 8) * AKS + cc) * 2) = __nv_bfloat162(h0, h1);
                *(__nv_bfloat162*)(sm + A_LO + ((r + 8) * AKS + cc) * 2) = __nv_bfloat162(l0, l1);
            }
        }
    }

    // ================= layer 3 (N=19, wn==0 warps compute) =================
#pragma unroll
    for (int t = 0; t < 2; t++)
#pragma unroll
        for (int u = 0; u < 4; u++)
#pragma unroll
            for (int q = 0; q < 4; q++) acc[t][u][q] = 0.f;

    for (int s = 0; s < HID / 32; s++) {
        __syncthreads();
        stage_w(sm, w3, HID, NC, 32, s * 32, tid);
        __syncthreads();
        if (wn == 0) {
#pragma unroll
            for (int half = 0; half < 2; half++) {
                int kg = s * 32 + half * 16, kl = half * 16;
                uint32_t ah[2][4], al[2][4];
#pragma unroll
                for (int t = 0; t < 2; t++) {
                    int r = wm * 32 + t * 16 + qrow;
                    ah[t][0] = lda(sm, A_HI, r,     kg + qk);
                    ah[t][1] = lda(sm, A_HI, r + 8, kg + qk);
                    ah[t][2] = lda(sm, A_HI, r,     kg + qk + 8);
                    ah[t][3] = lda(sm, A_HI, r + 8, kg + qk + 8);
                    al[t][0] = lda(sm, A_LO, r,     kg + qk);
                    al[t][1] = lda(sm, A_LO, r + 8, kg + qk);
                    al[t][2] = lda(sm, A_LO, r,     kg + qk + 8);
                    al[t][3] = lda(sm, A_LO, r + 8, kg + qk + 8);
                }
#pragma unroll
                for (int u = 0; u < 4; u++) {
                    int n = u * 8 + qrow;
                    uint32_t bh[2], bl[2];
                    bh[0] = ldw(sm, W_HI, n, kl + qk);
                    bh[1] = ldw(sm, W_HI, n, kl + qk + 8);
                    bl[0] = ldw(sm, W_LO, n, kl + qk);
                    bl[1] = ldw(sm, W_LO, n, kl + qk + 8);
#pragma unroll
                    for (int t = 0; t < 2; t++) {
                        mma16816(acc[t][u], ah[t], bh);
                        mma16816(acc[t][u], al[t], bh);
                        mma16816(acc[t][u], ah[t], bl);
                    }
                }
            }
        }
    }

    // scatter point logits
    if (wn == 0) {
#pragma unroll
        for (int t = 0; t < 2; t++) {
#pragma unroll
            for (int u = 0; u < 4; u++) {
                int cc = u * 8 + qk;
#pragma unroll
                for (int half = 0; half < 2; half++) {
                    int r = wm * 32 + t * 16 + qrow + half * 8;
                    int pix = sidx[r];
                    float v0 = acc[t][u][half * 2 + 0];
                    float v1 = acc[t][u][half * 2 + 1];
                    if (cc < NC)
                        out[((size_t)b * NC + cc) * HW + pix] = v0 + __ldg(&b3[cc]);
                    if (cc + 1 < NC)
                        out[((size_t)b * NC + cc + 1) * HW + pix] = v1 + __ldg(&b3[cc + 1]);
                }
            }
        }
    }
}

// ---------------- launch ----------------
extern "C" void kernel_launch(void* const* d_in, const int* in_sizes, int n_in,
                              void* d_out, int out_size)
{
    (void)in_sizes; (void)n_in; (void)out_size;
    const float* coarse = (const float*)d_in[0];
    const float* fine   = (const float*)d_in[1];
    const float* w1 = (const float*)d_in[2];
    const float* b1 = (const float*)d_in[3];
    const float* w2 = (const float*)d_in[4];
    const float* b2 = (const float*)d_in[5];
    const float* w3 = (const float*)d_in[6];
    const float* b3 = (const float*)d_in[7];
    float* out = (float*)d_out;

    static float* unc = nullptr;
    if (!unc) cudaGetSymbolAddress((void**)&unc, g_unc);
    static bool attr_done = false;
    if (!attr_done) {
        cudaFuncSetAttribute(mlp_mma_kernel,
                             cudaFuncAttributeMaxDynamicSharedMemorySize, SM_TOTAL);
        attr_done = true;
    }
    upsample_unc_kernel<<<B * HF, WF>>>(coarse, out, unc);
    topk_kernel<<<B, 1024>>>();
    mlp_mma_kernel<<<B * 16, 512, SM_TOTAL>>>(fine, w1, b1, w2, b2, w3, b3, out);
}

// round 7
// speedup vs baseline: 1.6687x; 1.0769x over previous
#include <cuda_runtime.h>
#include <cuda_bf16.h>
#include <cstdint>

constexpr int B = 8, NC = 19, HC = 32, WC = 64, CF = 256;
constexpr int HF = 128, WF = 256, HID = 256;
constexpr int HW = HF * WF, NPTS = 2048, CIN1 = CF + NC;   // 275
constexpr int K1P = 320;          // CIN1 padded to 32
constexpr int AKS = 328;          // A smem row stride (bf16 words)
constexpr int WKS = 40;           // W chunk row stride (bf16 words)

__device__ float g_unc[B * HW];
__device__ int   g_idx[B * NPTS];
__device__ int   g_tie[B * HW];

// ---------------- Kernel A: upsample + uncertainty ----------------
__global__ void __launch_bounds__(WF) upsample_unc_kernel(
    const float* __restrict__ coarse, float* __restrict__ out, float* __restrict__ unc)
{
    __shared__ float sm[NC * 128];
    int w = threadIdx.x, h = blockIdx.x & (HF - 1), b = blockIdx.x >> 7;
    float yf = (float)h * ((float)(HC - 1) / (float)(HF - 1));
    int y0 = min(max((int)floorf(yf), 0), HC - 1);
    int y1 = min(y0 + 1, HC - 1);
    float wy = yf - (float)y0;
    const float* cb = coarse + (size_t)b * NC * HC * WC;
    for (int j = w; j < NC * 128; j += WF) {
        int c = j >> 7, r = (j >> 6) & 1, x = j & 63;
        sm[j] = cb[c * (HC * WC) + (r ? y1 : y0) * WC + x];
    }
    __syncthreads();
    float xf = (float)w * ((float)(WC - 1) / (float)(WF - 1));
    int x0 = min(max((int)floorf(xf), 0), WC - 1);
    int x1 = min(x0 + 1, WC - 1);
    float wx = xf - (float)x0;
    float v[NC], vmax = -3.4e38f;
#pragma unroll
    for (int c = 0; c < NC; c++) {
        float r0 = sm[c*128 + x0] * (1.f - wy) + sm[c*128 + 64 + x0] * wy;
        float r1 = sm[c*128 + x1] * (1.f - wy) + sm[c*128 + 64 + x1] * wy;
        float val = r0 * (1.f - wx) + r1 * wx;
        v[c] = val; vmax = fmaxf(vmax, val);
        out[((size_t)(b * NC + c) * HF + h) * WF + w] = val;
    }
    float s = 0.f;
#pragma unroll
    for (int c = 0; c < NC; c++) s += expf(v[c] - vmax);
    unc[b * HW + h * WF + w] = -1.0f / s;
}

// ---------------- Kernel B: top-NPTS radix select (atomic-free hist) -------
__device__ __forceinline__ unsigned fkey(float f) {
    unsigned u = __float_as_uint(f);
    return (u & 0x80000000u) ? ~u : (u | 0x80000000u);
}
constexpr int KPT = HW / 1024;   // 32

__global__ void __launch_bounds__(1024) topk_kernel() {
    int b = blockIdx.x, tid = threadIdx.x, lane = tid & 31, wid = tid >> 5;
    const float* u = g_unc + b * HW;
    unsigned key[KPT];
#pragma unroll
    for (int i = 0; i < KPT; i++) key[i] = fkey(u[i * 1024 + tid]);

    __shared__ unsigned h32[32][257];       // per-warp histograms (no atomics)
    __shared__ unsigned hist[256];
    __shared__ unsigned s_prefix, s_mask;
    __shared__ int s_rem, cSel, cTie;
    if (tid == 0) { s_prefix = 0; s_mask = 0; s_rem = NPTS; cSel = 0; cTie = 0; }

    unsigned lmask_lt = (1u << lane) - 1u;

    for (int pass = 0; pass < 4; pass++) {
        int shift = (3 - pass) * 8;
        for (int j = tid; j < 32 * 257; j += 1024) ((unsigned*)h32)[j] = 0;
        __syncthreads();
        unsigned mask = s_mask, pref = s_prefix;
#pragma unroll
        for (int i = 0; i < KPT; i++) {
            unsigned k = key[i];
            bool act = (k & mask) == pref;
            unsigned bin = act ? ((k >> shift) & 255u) : 0xFFFFFFFFu;
            unsigned same = __match_any_sync(0xFFFFFFFFu, bin);
            if (act && (unsigned)(__ffs(same) - 1) == (unsigned)lane)
                h32[wid][bin] += (unsigned)__popc(same);   // warp-private: no atomic
        }
        __syncthreads();
        if (tid < 256) {
            unsigned s = 0;
#pragma unroll
            for (int w = 0; w < 32; w++) s += h32[w][tid];
            hist[tid] = s;
        }
        __syncthreads();
        if (tid == 0) {
            int need = s_rem; unsigned cum = 0; int sel = 0;
            for (int bin = 255; bin >= 0; bin--) {
                unsigned h = hist[bin];
                if (cum + h >= (unsigned)need) { sel = bin; s_rem = need - (int)cum; break; }
                cum += h;
            }
            s_prefix = pref | ((unsigned)sel << shift);
            s_mask = mask | (0xFFu << shift);
        }
        __syncthreads();
    }
    unsigned T = s_prefix;
    int R = s_rem;
    int* tie = g_tie + b * HW;

    // ---- aggregated scatter: 1 atomic per warp per class ----
    int nsel = 0, ntie = 0;
#pragma unroll
    for (int i = 0; i < KPT; i++) {
        nsel += __popc(__ballot_sync(0xFFFFFFFFu, key[i] > T));
        ntie += __popc(__ballot_sync(0xFFFFFFFFu, key[i] == T));
    }
    int wbS = 0, wbT = 0;
    if (lane == 0) {
        wbS = atomicAdd(&cSel, nsel);
        wbT = atomicAdd(&cTie, ntie);
    }
    wbS = __shfl_sync(0xFFFFFFFFu, wbS, 0);
    wbT = __shfl_sync(0xFFFFFFFFu, wbT, 0);
#pragma unroll
    for (int i = 0; i < KPT; i++) {
        unsigned k = key[i];
        int idx = i * 1024 + tid;
        unsigned sb = __ballot_sync(0xFFFFFFFFu, k > T);
        unsigned tb = __ballot_sync(0xFFFFFFFFu, k == T);
        if (k > T)       g_idx[b * NPTS + wbS + __popc(sb & lmask_lt)] = idx;
        else if (k == T) tie[wbT + __popc(tb & lmask_lt)] = idx;
        wbS += __popc(sb);
        wbT += __popc(tb);
    }
    __syncthreads();
    int E = cTie, base = cSel;
    for (int t = tid; t < E; t += 1024) {
        int my = tie[t], r = 0;
        for (int j = 0; j < E; j++) r += (tie[j] < my) ? 1 : 0;
        if (r < R) g_idx[b * NPTS + base + r] = my;
    }
}

// ---------------- MLP on mma.sync (bf16, 3-term split) ----------------
__device__ __forceinline__ void bf_split(float v, __nv_bfloat16& h, __nv_bfloat16& l) {
    h = __float2bfloat16(v);
    l = __float2bfloat16(v - __bfloat162float(h));
}

__device__ __forceinline__ void mma16816(float* d, const uint32_t* a, const uint32_t* b) {
    asm volatile(
        "mma.sync.aligned.m16n8k16.row.col.f32.bf16.bf16.f32 "
        "{%0,%1,%2,%3}, {%4,%5,%6,%7}, {%8,%9}, {%0,%1,%2,%3};"
        : "+f"(d[0]), "+f"(d[1]), "+f"(d[2]), "+f"(d[3])
        : "r"(a[0]), "r"(a[1]), "r"(a[2]), "r"(a[3]), "r"(b[0]), "r"(b[1]));
}

// smem byte offsets
constexpr int A_HI = 0;                              // 128*328*2 = 83968
constexpr int A_LO = 83968;
constexpr int W_HI = 167936;                         // 256*40*2 = 20480
constexpr int W_LO = 188416;
constexpr int S_IDX = 208896;                        // 128 ints
constexpr int SM_TOTAL = 209408 + 128;

__device__ __forceinline__ uint32_t lda(const char* sm, int base, int row, int col) {
    return *(const uint32_t*)(sm + base + (row * AKS + col) * 2);
}
__device__ __forceinline__ uint32_t ldw(const char* sm, int base, int n, int k) {
    return *(const uint32_t*)(sm + base + (n * WKS + k) * 2);
}

// prefetch a [ROWS][32] W chunk into registers (coalesced)
template <int ROWS>
__device__ __forceinline__ void ldW(float* r, const float* __restrict__ W,
                                    int cin, int nv, int k0, int tid)
{
    constexpr int CNT = ROWS * 32 / 512;
#pragma unroll
    for (int j = 0; j < CNT; j++) {
        int idx = tid + j * 512;
        int n = idx >> 5, kk = idx & 31, k = k0 + kk;
        r[j] = (n < nv && k < cin) ? W[n * cin + k] : 0.f;
    }
}
template <int ROWS>
__device__ __forceinline__ void stW(char* sm, const float* r, int tid)
{
    constexpr int CNT = ROWS * 32 / 512;
#pragma unroll
    for (int j = 0; j < CNT; j++) {
        int idx = tid + j * 512;
        int n = idx >> 5, kk = idx & 31;
        __nv_bfloat16 h, l; bf_split(r[j], h, l);
        *(__nv_bfloat16*)(sm + W_HI + (n * WKS + kk) * 2) = h;
        *(__nv_bfloat16*)(sm + W_LO + (n * WKS + kk) * 2) = l;
    }
}

__global__ void __launch_bounds__(512, 1) mlp_mma_kernel(
    const float* __restrict__ fine,
    const float* __restrict__ w1, const float* __restrict__ b1,
    const float* __restrict__ w2, const float* __restrict__ b2,
    const float* __restrict__ w3, const float* __restrict__ b3,
    float* __restrict__ out)
{
    extern __shared__ char sm[];
    int tid = threadIdx.x, wid = tid >> 5, lane = tid & 31;
    int wm = wid & 3, wn = wid >> 2;           // warp tile: rows 32*wm, cols 64*wn
    int b = blockIdx.x >> 4, tb = blockIdx.x & 15;
    int* sidx = (int*)(sm + S_IDX);

    if (tid < 128) sidx[tid] = g_idx[b * NPTS + tb * 128 + tid];
    __syncthreads();

    // ---- gather A[p][c] (hi/lo split) ----
    for (int idx = tid; idx < K1P * 128; idx += 512) {
        int p = idx & 127, c = idx >> 7;
        float v = 0.f;
        if (c < CF)        v = fine[((size_t)b * CF + c) * HW + sidx[p]];
        else if (c < CIN1) v = out[((size_t)b * NC + (c - CF)) * HW + sidx[p]];
        __nv_bfloat16 h, l; bf_split(v, h, l);
        *(__nv_bfloat16*)(sm + A_HI + (p * AKS + c) * 2) = h;
        *(__nv_bfloat16*)(sm + A_LO + (p * AKS + c) * 2) = l;
    }

    float acc[2][8][4];
    float rw[16];
    int qrow = lane >> 2, qk = 2 * (lane & 3);

    // ================= layers 1 & 2 =================
#pragma unroll 1
    for (int layer = 0; layer < 2; layer++) {
        const float* W   = layer ? w2 : w1;
        const float* bia = layer ? b2 : b1;
        int cin   = layer ? HID : CIN1;
        int kpad  = layer ? HID : K1P;
        int nstg  = kpad / 32;
#pragma unroll
        for (int t = 0; t < 2; t++)
#pragma unroll
            for (int u = 0; u < 8; u++)
#pragma unroll
                for (int q = 0; q < 4; q++) acc[t][u][q] = 0.f;

        ldW<256>(rw, W, cin, 256, 0, tid);
        for (int s = 0; s < nstg; s++) {
            __syncthreads();                       // prior mma done -> W overwrite safe
            stW<256>(sm, rw, tid);
            if (s + 1 < nstg) ldW<256>(rw, W, cin, 256, (s + 1) * 32, tid);
            __syncthreads();
#pragma unroll
            for (int half = 0; half < 2; half++) {
                int kg = s * 32 + half * 16;       // global k into A
                int kl = half * 16;                // local k into W chunk
                uint32_t ah[2][4], al[2][4];
#pragma unroll
                for (int t = 0; t < 2; t++) {
                    int r = wm * 32 + t * 16 + qrow;
                    ah[t][0] = lda(sm, A_HI, r,     kg + qk);
                    ah[t][1] = lda(sm, A_HI, r + 8, kg + qk);
                    ah[t][2] = lda(sm, A_HI, r,     kg + qk + 8);
                    ah[t][3] = lda(sm, A_HI, r + 8, kg + qk + 8);
                    al[t][0] = lda(sm, A_LO, r,     kg + qk);
                    al[t][1] = lda(sm, A_LO, r + 8, kg + qk);
                    al[t][2] = lda(sm, A_LO, r,     kg + qk + 8);
                    al[t][3] = lda(sm, A_LO, r + 8, kg + qk + 8);
                }
#pragma unroll
                for (int u = 0; u < 8; u++) {
                    int n = wn * 64 + u * 8 + qrow;
                    uint32_t bh[2], bl[2];
                    bh[0] = ldw(sm, W_HI, n, kl + qk);
                    bh[1] = ldw(sm, W_HI, n, kl + qk + 8);
                    bl[0] = ldw(sm, W_LO, n, kl + qk);
                    bl[1] = ldw(sm, W_LO, n, kl + qk + 8);
#pragma unroll
                    for (int t = 0; t < 2; t++) {
                        mma16816(acc[t][u], ah[t], bh);
                        mma16816(acc[t][u], al[t], bh);
                        mma16816(acc[t][u], ah[t], bl);
                    }
                }
            }
        }
        __syncthreads();    // all mma reads of A done before overwrite

        // epilogue: bias + relu + split back into A
#pragma unroll
        for (int t = 0; t < 2; t++) {
#pragma unroll
            for (int u = 0; u < 8; u++) {
                int r  = wm * 32 + t * 16 + qrow;
                int cc = wn * 64 + u * 8 + qk;
                float bb0 = __ldg(&bia[cc]), bb1 = __ldg(&bia[cc + 1]);
                float v0 = fmaxf(acc[t][u][0] + bb0, 0.f);
                float v1 = fmaxf(acc[t][u][1] + bb1, 0.f);
                float v2 = fmaxf(acc[t][u][2] + bb0, 0.f);
                float v3 = fmaxf(acc[t][u][3] + bb1, 0.f);
                __nv_bfloat16 h0, l0, h1, l1;
                bf_split(v0, h0, l0); bf_split(v1, h1, l1);
                *(__nv_bfloat162*)(sm + A_HI + (r * AKS + cc) * 2) = __nv_bfloat162(h0, h1);
                *(__nv_bfloat162*)(sm + A_LO + (r * AKS + cc) * 2) = __nv_bfloat162(l0, l1);
                bf_split(v2, h0, l0); bf_split(v3, h1, l1);
                *(__nv_bfloat162*)(sm + A_HI + ((r + 8) * AKS + cc) * 2) = __nv_bfloat162(h0, h1);
                *(__nv_bfloat162*)(sm + A_LO + ((r + 8) * AKS + cc) * 2) = __nv_bfloat162(l0, l1);
            }
        }
    }

    // ================= layer 3 (N=19, wn==0 warps compute) =================
#pragma unroll
    for (int t = 0; t < 2; t++)
#pragma unroll
        for (int u = 0; u < 4; u++)
#pragma unroll
            for (int q = 0; q < 4; q++) acc[t][u][q] = 0.f;

    ldW<32>(rw, w3, HID, NC, 0, tid);
    for (int s = 0; s < HID / 32; s++) {
        __syncthreads();
        stW<32>(sm, rw, tid);
        if (s + 1 < HID / 32) ldW<32>(rw, w3, HID, NC, (s + 1) * 32, tid);
        __syncthreads();
        if (wn == 0) {
#pragma unroll
            for (int half = 0; half < 2; half++) {
                int kg = s * 32 + half * 16, kl = half * 16;
                uint32_t ah[2][4], al[2][4];
#pragma unroll
                for (int t = 0; t < 2; t++) {
                    int r = wm * 32 + t * 16 + qrow;
                    ah[t][0] = lda(sm, A_HI, r,     kg + qk);
                    ah[t][1] = lda(sm, A_HI, r + 8, kg + qk);
                    ah[t][2] = lda(sm, A_HI, r,     kg + qk + 8);
                    ah[t][3] = lda(sm, A_HI, r + 8, kg + qk + 8);
                    al[t][0] = lda(sm, A_LO, r,     kg + qk);
                    al[t][1] = lda(sm, A_LO, r + 8, kg + qk);
                    al[t][2] = lda(sm, A_LO, r,     kg + qk + 8);
                    al[t][3] = lda(sm, A_LO, r + 8, kg + qk + 8);
                }
#pragma unroll
                for (int u = 0; u < 4; u++) {
                    int n = u * 8 + qrow;
                    uint32_t bh[2], bl[2];
                    bh[0] = ldw(sm, W_HI, n, kl + qk);
                    bh[1] = ldw(sm, W_HI, n, kl + qk + 8);
                    bl[0] = ldw(sm, W_LO, n, kl + qk);
                    bl[1] = ldw(sm, W_LO, n, kl + qk + 8);
#pragma unroll
                    for (int t = 0; t < 2; t++) {
                        mma16816(acc[t][u], ah[t], bh);
                        mma16816(acc[t][u], al[t], bh);
                        mma16816(acc[t][u], ah[t], bl);
                    }
                }
            }
        }
    }

    // scatter point logits
    if (wn == 0) {
#pragma unroll
        for (int t = 0; t < 2; t++) {
#pragma unroll
            for (int u = 0; u < 4; u++) {
                int cc = u * 8 + qk;
#pragma unroll
                for (int half = 0; half < 2; half++) {
                    int r = wm * 32 + t * 16 + qrow + half * 8;
                    int pix = sidx[r];
                    float v0 = acc[t][u][half * 2 + 0];
                    float v1 = acc[t][u][half * 2 + 1];
                    if (cc < NC)
                        out[((size_t)b * NC + cc) * HW + pix] = v0 + __ldg(&b3[cc]);
                    if (cc + 1 < NC)
                        out[((size_t)b * NC + cc + 1) * HW + pix] = v1 + __ldg(&b3[cc + 1]);
                }
            }
        }
    }
}

// ---------------- launch ----------------
extern "C" void kernel_launch(void* const* d_in, const int* in_sizes, int n_in,
                              void* d_out, int out_size)
{
    (void)in_sizes; (void)n_in; (void)out_size;
    const float* coarse = (const float*)d_in[0];
    const float* fine   = (const float*)d_in[1];
    const float* w1 = (const float*)d_in[2];
    const float* b1 = (const float*)d_in[3];
    const float* w2 = (const float*)d_in[4];
    const float* b2 = (const float*)d_in[5];
    const float* w3 = (const float*)d_in[6];
    const float* b3 = (const float*)d_in[7];
    float* out = (float*)d_out;

    static float* unc = nullptr;
    if (!unc) cudaGetSymbolAddress((void**)&unc, g_unc);
    static bool attr_done = false;
    if (!attr_done) {
        cudaFuncSetAttribute(mlp_mma_kernel,
                             cudaFuncAttributeMaxDynamicSharedMemorySize, SM_TOTAL);
        attr_done = true;
    }
    upsample_unc_kernel<<<B * HF, WF>>>(coarse, out, unc);
    topk_kernel<<<B, 1024>>>();
    mlp_mma_kernel<<<B * 16, 512, SM_TOTAL>>>(fine, w1, b1, w2, b2, w3, b3, out);
}

// round 8
// speedup vs baseline: 1.8816x; 1.1276x over previous
#include <cuda_runtime.h>
#include <cuda_fp16.h>
#include <cstdint>

constexpr int B = 8, NC = 19, HC = 32, WC = 64, CF = 256;
constexpr int HF = 128, WF = 256, HID = 256;
constexpr int HW = HF * WF, NPTS = 2048, CIN1 = CF + NC;   // 275
constexpr int K1P = 320;          // CIN1 padded
constexpr int AKS = 328;          // A smem row stride (fp16 words)
constexpr int WKS = 72;           // W chunk row stride (fp16 words), K64 chunk

__device__ float g_unc[B * HW];
__device__ int   g_idx[B * NPTS];
__device__ int   g_tie[B * HW];
__device__ __half g_W1h[256 * K1P];
__device__ __half g_W2h[256 * 256];
__device__ __half g_W3h[32 * 256];

// ---------------- Kernel P: pre-split weights to fp16 ----------------
__global__ void __launch_bounds__(256) prep_weights(
    const float* __restrict__ w1, const float* __restrict__ w2,
    const float* __restrict__ w3)
{
    constexpr int T1 = 256 * K1P, T2 = 256 * 256, T3 = 32 * 256;
    for (int i = blockIdx.x * 256 + threadIdx.x; i < T1 + T2 + T3;
         i += gridDim.x * 256) {
        if (i < T1) {
            int n = i / K1P, k = i - n * K1P;
            g_W1h[i] = __float2half_rn(k < CIN1 ? w1[n * CIN1 + k] : 0.f);
        } else if (i < T1 + T2) {
            int j = i - T1;
            g_W2h[j] = __float2half_rn(w2[j]);
        } else {
            int j = i - T1 - T2;
            int n = j >> 8, k = j & 255;
            g_W3h[j] = __float2half_rn(n < NC ? w3[n * HID + k] : 0.f);
        }
    }
}

// ---------------- Kernel A: upsample + uncertainty ----------------
__global__ void __launch_bounds__(WF) upsample_unc_kernel(
    const float* __restrict__ coarse, float* __restrict__ out, float* __restrict__ unc)
{
    __shared__ float sm[NC * 128];
    int w = threadIdx.x, h = blockIdx.x & (HF - 1), b = blockIdx.x >> 7;
    float yf = (float)h * ((float)(HC - 1) / (float)(HF - 1));
    int y0 = min(max((int)floorf(yf), 0), HC - 1);
    int y1 = min(y0 + 1, HC - 1);
    float wy = yf - (float)y0;
    const float* cb = coarse + (size_t)b * NC * HC * WC;
    for (int j = w; j < NC * 128; j += WF) {
        int c = j >> 7, r = (j >> 6) & 1, x = j & 63;
        sm[j] = cb[c * (HC * WC) + (r ? y1 : y0) * WC + x];
    }
    __syncthreads();
    float xf = (float)w * ((float)(WC - 1) / (float)(WF - 1));
    int x0 = min(max((int)floorf(xf), 0), WC - 1);
    int x1 = min(x0 + 1, WC - 1);
    float wx = xf - (float)x0;
    float v[NC], vmax = -3.4e38f;
#pragma unroll
    for (int c = 0; c < NC; c++) {
        float r0 = sm[c*128 + x0] * (1.f - wy) + sm[c*128 + 64 + x0] * wy;
        float r1 = sm[c*128 + x1] * (1.f - wy) + sm[c*128 + 64 + x1] * wy;
        float val = r0 * (1.f - wx) + r1 * wx;
        v[c] = val; vmax = fmaxf(vmax, val);
        out[((size_t)(b * NC + c) * HF + h) * WF + w] = val;
    }
    float s = 0.f;
#pragma unroll
    for (int c = 0; c < NC; c++) s += __expf(v[c] - vmax);
    unc[b * HW + h * WF + w] = -1.0f / s;
}

// ---------------- Kernel B: top-NPTS radix select ----------------
__device__ __forceinline__ unsigned fkey(float f) {
    unsigned u = __float_as_uint(f);
    return (u & 0x80000000u) ? ~u : (u | 0x80000000u);
}
constexpr int KPT = HW / 1024;   // 32

__global__ void __launch_bounds__(1024) topk_kernel() {
    int b = blockIdx.x, tid = threadIdx.x, lane = tid & 31, wid = tid >> 5;
    const float* u = g_unc + b * HW;
    unsigned key[KPT];
#pragma unroll
    for (int i = 0; i < KPT; i++) key[i] = fkey(u[i * 1024 + tid]);

    __shared__ unsigned h32[32][257];
    __shared__ unsigned hist[256];
    __shared__ unsigned s_prefix, s_mask;
    __shared__ int s_rem, cSel, cTie;
    if (tid == 0) { s_prefix = 0; s_mask = 0; s_rem = NPTS; cSel = 0; cTie = 0; }

    unsigned lmask_lt = (1u << lane) - 1u;

    for (int pass = 0; pass < 4; pass++) {
        int shift = (3 - pass) * 8;
        for (int j = tid; j < 32 * 257; j += 1024) ((unsigned*)h32)[j] = 0;
        __syncthreads();
        unsigned mask = s_mask, pref = s_prefix;
#pragma unroll
        for (int i = 0; i < KPT; i++) {
            unsigned k = key[i];
            bool act = (k & mask) == pref;
            unsigned bin = act ? ((k >> shift) & 255u) : 0xFFFFFFFFu;
            unsigned same = __match_any_sync(0xFFFFFFFFu, bin);
            if (act && (unsigned)(__ffs(same) - 1) == (unsigned)lane)
                h32[wid][bin] += (unsigned)__popc(same);
        }
        __syncthreads();
        if (tid < 256) {
            unsigned s = 0;
#pragma unroll
            for (int w = 0; w < 32; w++) s += h32[w][tid];
            hist[tid] = s;
        }
        __syncthreads();
        if (tid == 0) {
            int need = s_rem; unsigned cum = 0; int sel = 0;
            for (int bin = 255; bin >= 0; bin--) {
                unsigned h = hist[bin];
                if (cum + h >= (unsigned)need) { sel = bin; s_rem = need - (int)cum; break; }
                cum += h;
            }
            s_prefix = pref | ((unsigned)sel << shift);
            s_mask = mask | (0xFFu << shift);
        }
        __syncthreads();
    }
    unsigned T = s_prefix;
    int R = s_rem;
    int* tie = g_tie + b * HW;

    int nsel = 0, ntie = 0;
#pragma unroll
    for (int i = 0; i < KPT; i++) {
        nsel += __popc(__ballot_sync(0xFFFFFFFFu, key[i] > T));
        ntie += __popc(__ballot_sync(0xFFFFFFFFu, key[i] == T));
    }
    int wbS = 0, wbT = 0;
    if (lane == 0) {
        wbS = atomicAdd(&cSel, nsel);
        wbT = atomicAdd(&cTie, ntie);
    }
    wbS = __shfl_sync(0xFFFFFFFFu, wbS, 0);
    wbT = __shfl_sync(0xFFFFFFFFu, wbT, 0);
#pragma unroll
    for (int i = 0; i < KPT; i++) {
        unsigned k = key[i];
        int idx = i * 1024 + tid;
        unsigned sb = __ballot_sync(0xFFFFFFFFu, k > T);
        unsigned tb = __ballot_sync(0xFFFFFFFFu, k == T);
        if (k > T)       g_idx[b * NPTS + wbS + __popc(sb & lmask_lt)] = idx;
        else if (k == T) tie[wbT + __popc(tb & lmask_lt)] = idx;
        wbS += __popc(sb);
        wbT += __popc(tb);
    }
    __syncthreads();
    int E = cTie, base = cSel;
    for (int t = tid; t < E; t += 1024) {
        int my = tie[t], r = 0;
        for (int j = 0; j < E; j++) r += (tie[j] < my) ? 1 : 0;
        if (r < R) g_idx[b * NPTS + base + r] = my;
    }
}

// ---------------- MLP on mma.sync (fp16, 2-term A split) ----------------
__device__ __forceinline__ void h_split(float v, __half& h, __half& l) {
    h = __float2half_rn(v);
    l = __float2half_rn(v - __half2float(h));
}

__device__ __forceinline__ void mma16816(float* d, const uint32_t* a, const uint32_t* b) {
    asm volatile(
        "mma.sync.aligned.m16n8k16.row.col.f32.f16.f16.f32 "
        "{%0,%1,%2,%3}, {%4,%5,%6,%7}, {%8,%9}, {%0,%1,%2,%3};"
        : "+f"(d[0]), "+f"(d[1]), "+f"(d[2]), "+f"(d[3])
        : "r"(a[0]), "r"(a[1]), "r"(a[2]), "r"(a[3]), "r"(b[0]), "r"(b[1]));
}

// smem byte offsets
constexpr int A_HI = 0;                              // 128*328*2 = 83968
constexpr int A_LO = 83968;
constexpr int W_SM = 167936;                         // 256*72*2 = 36864
constexpr int S_IDX = 204800;                        // 128 ints
constexpr int SM_TOTAL = 205312 + 128;

__device__ __forceinline__ uint32_t lda(const char* sm, int base, int row, int col) {
    return *(const uint32_t*)(sm + base + (row * AKS + col) * 2);
}
__device__ __forceinline__ uint32_t ldw(const char* sm, int n, int k) {
    return *(const uint32_t*)(sm + W_SM + (n * WKS + k) * 2);
}

// register-prefetch a [256][64] fp16 W chunk (4 uint4/thread)
__device__ __forceinline__ void ldW256(uint4* r, const __half* __restrict__ W,
                                       int wstr, int k0, int tid)
{
#pragma unroll
    for (int j = 0; j < 4; j++) {
        int idx = tid + j * 512;
        int row = idx >> 3, q = idx & 7;
        r[j] = *(const uint4*)(W + row * wstr + k0 + q * 8);
    }
}
__device__ __forceinline__ void stW256(char* sm, const uint4* r, int tid)
{
#pragma unroll
    for (int j = 0; j < 4; j++) {
        int idx = tid + j * 512;
        int row = idx >> 3, q = idx & 7;
        *(uint4*)(sm + W_SM + (row * WKS + q * 8) * 2) = r[j];
    }
}

__global__ void __launch_bounds__(512, 1) mlp_mma_kernel(
    const float* __restrict__ fine,
    const float* __restrict__ b1, const float* __restrict__ b2,
    const float* __restrict__ b3, float* __restrict__ out)
{
    extern __shared__ char sm[];
    int tid = threadIdx.x, wid = tid >> 5, lane = tid & 31;
    int wm = wid & 3, wn = wid >> 2;
    int b = blockIdx.x >> 4, tb = blockIdx.x & 15;
    int* sidx = (int*)(sm + S_IDX);

    if (tid < 128) sidx[tid] = g_idx[b * NPTS + tb * 128 + tid];
    __syncthreads();

    // ---- gather A[p][c] (fp16 hi/lo split) ----
    for (int idx = tid; idx < K1P * 128; idx += 512) {
        int p = idx & 127, c = idx >> 7;
        float v = 0.f;
        if (c < CF)        v = fine[((size_t)b * CF + c) * HW + sidx[p]];
        else if (c < CIN1) v = out[((size_t)b * NC + (c - CF)) * HW + sidx[p]];
        __half h, l; h_split(v, h, l);
        *(__half*)(sm + A_HI + (p * AKS + c) * 2) = h;
        *(__half*)(sm + A_LO + (p * AKS + c) * 2) = l;
    }

    float acc[2][8][4];
    uint4 rwv[4];
    int qrow = lane >> 2, qk = 2 * (lane & 3);

    // ================= layers 1 & 2 =================
#pragma unroll 1
    for (int layer = 0; layer < 2; layer++) {
        const __half* Wg = layer ? g_W2h : g_W1h;
        const float* bia = layer ? b2 : b1;
        int wstr = layer ? 256 : K1P;
        int nstg = wstr / 64;                 // 4 or 5
#pragma unroll
        for (int t = 0; t < 2; t++)
#pragma unroll
            for (int u = 0; u < 8; u++)
#pragma unroll
                for (int q = 0; q < 4; q++) acc[t][u][q] = 0.f;

        ldW256(rwv, Wg, wstr, 0, tid);
        for (int s = 0; s < nstg; s++) {
            __syncthreads();
            stW256(sm, rwv, tid);
            if (s + 1 < nstg) ldW256(rwv, Wg, wstr, (s + 1) * 64, tid);
            __syncthreads();
#pragma unroll
            for (int half = 0; half < 4; half++) {
                int kg = s * 64 + half * 16;
                int kl = half * 16;
                uint32_t ah[2][4], al[2][4];
#pragma unroll
                for (int t = 0; t < 2; t++) {
                    int r = wm * 32 + t * 16 + qrow;
                    ah[t][0] = lda(sm, A_HI, r,     kg + qk);
                    ah[t][1] = lda(sm, A_HI, r + 8, kg + qk);
                    ah[t][2] = lda(sm, A_HI, r,     kg + qk + 8);
                    ah[t][3] = lda(sm, A_HI, r + 8, kg + qk + 8);
                    al[t][0] = lda(sm, A_LO, r,     kg + qk);
                    al[t][1] = lda(sm, A_LO, r + 8, kg + qk);
                    al[t][2] = lda(sm, A_LO, r,     kg + qk + 8);
                    al[t][3] = lda(sm, A_LO, r + 8, kg + qk + 8);
                }
#pragma unroll
                for (int u = 0; u < 8; u++) {
                    int n = wn * 64 + u * 8 + qrow;
                    uint32_t bh[2];
                    bh[0] = ldw(sm, n, kl + qk);
                    bh[1] = ldw(sm, n, kl + qk + 8);
#pragma unroll
                    for (int t = 0; t < 2; t++) {
                        mma16816(acc[t][u], ah[t], bh);
                        mma16816(acc[t][u], al[t], bh);
                    }
                }
            }
        }
        __syncthreads();

        // epilogue: bias + relu + fp16 split back into A
#pragma unroll
        for (int t = 0; t < 2; t++) {
#pragma unroll
            for (int u = 0; u < 8; u++) {
                int r  = wm * 32 + t * 16 + qrow;
                int cc = wn * 64 + u * 8 + qk;
                float bb0 = __ldg(&bia[cc]), bb1 = __ldg(&bia[cc + 1]);
                float v0 = fmaxf(acc[t][u][0] + bb0, 0.f);
                float v1 = fmaxf(acc[t][u][1] + bb1, 0.f);
                float v2 = fmaxf(acc[t][u][2] + bb0, 0.f);
                float v3 = fmaxf(acc[t][u][3] + bb1, 0.f);
                __half h0, l0, h1, l1;
                h_split(v0, h0, l0); h_split(v1, h1, l1);
                *(__half2*)(sm + A_HI + (r * AKS + cc) * 2) = __half2(h0, h1);
                *(__half2*)(sm + A_LO + (r * AKS + cc) * 2) = __half2(l0, l1);
                h_split(v2, h0, l0); h_split(v3, h1, l1);
                *(__half2*)(sm + A_HI + ((r + 8) * AKS + cc) * 2) = __half2(h0, h1);
                *(__half2*)(sm + A_LO + ((r + 8) * AKS + cc) * 2) = __half2(l0, l1);
            }
        }
    }

    // ================= layer 3 (N=19 padded 32, wn==0 computes) ============
#pragma unroll
    for (int t = 0; t < 2; t++)
#pragma unroll
        for (int u = 0; u < 4; u++)
#pragma unroll
            for (int q = 0; q < 4; q++) acc[t][u][q] = 0.f;

    for (int s = 0; s < 4; s++) {
        __syncthreads();
        if (tid < 256) {
            int row = tid >> 3, q = tid & 7;
            uint4 v = *(const uint4*)(g_W3h + row * 256 + s * 64 + q * 8);
            *(uint4*)(sm + W_SM + (row * WKS + q * 8) * 2) = v;
        }
        __syncthreads();
        if (wn == 0) {
#pragma unroll
            for (int half = 0; half < 4; half++) {
                int kg = s * 64 + half * 16, kl = half * 16;
                uint32_t ah[2][4], al[2][4];
#pragma unroll
                for (int t = 0; t < 2; t++) {
                    int r = wm * 32 + t * 16 + qrow;
                    ah[t][0] = lda(sm, A_HI, r,     kg + qk);
                    ah[t][1] = lda(sm, A_HI, r + 8, kg + qk);
                    ah[t][2] = lda(sm, A_HI, r,     kg + qk + 8);
                    ah[t][3] = lda(sm, A_HI, r + 8, kg + qk + 8);
                    al[t][0] = lda(sm, A_LO, r,     kg + qk);
                    al[t][1] = lda(sm, A_LO, r + 8, kg + qk);
                    al[t][2] = lda(sm, A_LO, r,     kg + qk + 8);
                    al[t][3] = lda(sm, A_LO, r + 8, kg + qk + 8);
                }
#pragma unroll
                for (int u = 0; u < 4; u++) {
                    int n = u * 8 + qrow;
                    uint32_t bh[2];
                    bh[0] = ldw(sm, n, kl + qk);
                    bh[1] = ldw(sm, n, kl + qk + 8);
#pragma unroll
                    for (int t = 0; t < 2; t++) {
                        mma16816(acc[t][u], ah[t], bh);
                        mma16816(acc[t][u], al[t], bh);
                    }
                }
            }
        }
    }

    // scatter point logits
    if (wn == 0) {
#pragma unroll
        for (int t = 0; t < 2; t++) {
#pragma unroll
            for (int u = 0; u < 4; u++) {
                int cc = u * 8 + qk;
#pragma unroll
                for (int half = 0; half < 2; half++) {
                    int r = wm * 32 + t * 16 + qrow + half * 8;
                    int pix = sidx[r];
                    float v0 = acc[t][u][half * 2 + 0];
                    float v1 = acc[t][u][half * 2 + 1];
                    if (cc < NC)
                        out[((size_t)b * NC + cc) * HW + pix] = v0 + __ldg(&b3[cc]);
                    if (cc + 1 < NC)
                        out[((size_t)b * NC + cc + 1) * HW + pix] = v1 + __ldg(&b3[cc + 1]);
                }
            }
        }
    }
}

// ---------------- launch ----------------
extern "C" void kernel_launch(void* const* d_in, const int* in_sizes, int n_in,
                              void* d_out, int out_size)
{
    (void)in_sizes; (void)n_in; (void)out_size;
    const float* coarse = (const float*)d_in[0];
    const float* fine   = (const float*)d_in[1];
    const float* w1 = (const float*)d_in[2];
    const float* b1 = (const float*)d_in[3];
    const float* w2 = (const float*)d_in[4];
    const float* b2 = (const float*)d_in[5];
    const float* w3 = (const float*)d_in[6];
    const float* b3 = (const float*)d_in[7];
    float* out = (float*)d_out;

    static float* unc = nullptr;
    if (!unc) cudaGetSymbolAddress((void**)&unc, g_unc);
    static bool attr_done = false;
    if (!attr_done) {
        cudaFuncSetAttribute(mlp_mma_kernel,
                             cudaFuncAttributeMaxDynamicSharedMemorySize, SM_TOTAL);
        attr_done = true;
    }
    prep_weights<<<152, 256>>>(w1, w2, w3);
    upsample_unc_kernel<<<B * HF, WF>>>(coarse, out, unc);
    topk_kernel<<<B, 1024>>>();
    mlp_mma_kernel<<<B * 16, 512, SM_TOTAL>>>(fine, b1, b2, b3, out);
}